// round 1
// baseline (speedup 1.0000x reference)
#include <cuda_runtime.h>

#define N_PIX 4096
#define BATCH 4
#define CH    256
#define DQK   32

typedef unsigned long long u64;

// ---------------- scratch (device globals; no allocation in kernel_launch) ---------
__device__ float g_q[(size_t)BATCH * N_PIX * DQK];   // [b][n][d]   2 MB
__device__ float g_k[(size_t)BATCH * N_PIX * DQK];   // [b][m][d]   2 MB
__device__ float g_v[(size_t)BATCH * CH * N_PIX];    // [b][d][m]  16 MB
__device__ float g_p[(size_t)BATCH * N_PIX * N_PIX]; // [b][n][m] 256 MB

// ---------------- f32x2 helpers (FFMA2 only reachable via PTX) ---------------------
__device__ __forceinline__ u64 fma2(u64 a, u64 b, u64 c) {
    u64 d;
    asm("fma.rn.f32x2 %0, %1, %2, %3;" : "=l"(d) : "l"(a), "l"(b), "l"(c));
    return d;
}
__device__ __forceinline__ u64 pack2(float x, float y) {
    u64 r;
    asm("mov.b64 %0, {%1, %2};" : "=l"(r) : "f"(x), "f"(y));
    return r;
}
__device__ __forceinline__ float2 unpack2(u64 v) {
    float2 r;
    asm("mov.b64 {%0, %1}, %2;" : "=f"(r.x), "=f"(r.y) : "l"(v));
    return r;
}

// ================== kernel 1: q/k projection =======================================
// q[b,n,d] = sum_c Wq[d,c] x[b,c,n] + bq[d];  k likewise. One thread per pixel n.
__global__ void __launch_bounds__(256) proj_qk_kernel(
    const float* __restrict__ x,
    const float* __restrict__ Wq, const float* __restrict__ bq,
    const float* __restrict__ Wk, const float* __restrict__ bk)
{
    __shared__ float sWq[32 * 128];
    __shared__ float sWk[32 * 128];

    int b = blockIdx.y;
    int n = blockIdx.x * 256 + threadIdx.x;

    float qa[32], ka[32];
#pragma unroll
    for (int d = 0; d < 32; d++) { qa[d] = 0.f; ka[d] = 0.f; }

    const float* xb = x + (size_t)b * CH * N_PIX + n;

    for (int ch = 0; ch < 2; ch++) {
        for (int i = threadIdx.x; i < 32 * 128; i += 256) {
            int d = i >> 7, c = i & 127;
            sWq[i] = Wq[d * CH + ch * 128 + c];
            sWk[i] = Wk[d * CH + ch * 128 + c];
        }
        __syncthreads();

        const float* xc = xb + (size_t)ch * 128 * N_PIX;
        for (int c = 0; c < 128; c += 4) {
            float x0 = xc[(size_t)(c + 0) * N_PIX];
            float x1 = xc[(size_t)(c + 1) * N_PIX];
            float x2 = xc[(size_t)(c + 2) * N_PIX];
            float x3 = xc[(size_t)(c + 3) * N_PIX];
#pragma unroll
            for (int d = 0; d < 32; d++) {
                float4 wq = *(const float4*)&sWq[d * 128 + c];
                qa[d] += wq.x * x0; qa[d] += wq.y * x1;
                qa[d] += wq.z * x2; qa[d] += wq.w * x3;
                float4 wk = *(const float4*)&sWk[d * 128 + c];
                ka[d] += wk.x * x0; ka[d] += wk.y * x1;
                ka[d] += wk.z * x2; ka[d] += wk.w * x3;
            }
        }
        __syncthreads();
    }

    float* qo = g_q + ((size_t)b * N_PIX + n) * DQK;
    float* ko = g_k + ((size_t)b * N_PIX + n) * DQK;
#pragma unroll
    for (int d = 0; d < 32; d += 4) {
        *(float4*)(qo + d) = make_float4(qa[d] + bq[d], qa[d + 1] + bq[d + 1],
                                         qa[d + 2] + bq[d + 2], qa[d + 3] + bq[d + 3]);
        *(float4*)(ko + d) = make_float4(ka[d] + bk[d], ka[d + 1] + bk[d + 1],
                                         ka[d + 2] + bk[d + 2], ka[d + 3] + bk[d + 3]);
    }
}

// ================== kernel 2: v projection (tiled GEMM 256x4096x256 per batch) =====
__global__ void __launch_bounds__(256) proj_v_kernel(
    const float* __restrict__ x, const float* __restrict__ Wv, const float* __restrict__ bv)
{
    __shared__ float sA[32][68];  // [c][d]  (Wv transposed)
    __shared__ float sB[32][68];  // [c][n]

    int b  = blockIdx.z;
    int n0 = blockIdx.x * 64;
    int d0 = blockIdx.y * 64;
    int tx = threadIdx.x, ty = threadIdx.y, tid = ty * 16 + tx;

    float acc[4][4] = {};

    for (int c0 = 0; c0 < CH; c0 += 32) {
        for (int idx = tid; idx < 512; idx += 256) {
            int r = idx >> 3, q = idx & 7;   // Wv tile: r = d (0..63), q = c/4 (0..7)
            float4 w = *(const float4*)(Wv + (size_t)(d0 + r) * CH + c0 + q * 4);
            sA[q * 4 + 0][r] = w.x; sA[q * 4 + 1][r] = w.y;
            sA[q * 4 + 2][r] = w.z; sA[q * 4 + 3][r] = w.w;

            int r2 = idx >> 4, q2 = idx & 15; // x tile: r2 = c (0..31), q2 = n/4 (0..15)
            float4 xv = *(const float4*)(x + ((size_t)b * CH + c0 + r2) * N_PIX + n0 + q2 * 4);
            *(float4*)&sB[r2][q2 * 4] = xv;
        }
        __syncthreads();

#pragma unroll
        for (int k = 0; k < 32; k++) {
            float4 a4 = *(const float4*)&sA[k][ty * 4];
            float4 b4 = *(const float4*)&sB[k][tx * 4];
            float av[4] = {a4.x, a4.y, a4.z, a4.w};
            float bw[4] = {b4.x, b4.y, b4.z, b4.w};
#pragma unroll
            for (int i = 0; i < 4; i++)
#pragma unroll
                for (int j = 0; j < 4; j++)
                    acc[i][j] += av[i] * bw[j];
        }
        __syncthreads();
    }

#pragma unroll
    for (int i = 0; i < 4; i++) {
        int d = d0 + ty * 4 + i;
        float bias = bv[d];
        float4 o = make_float4(acc[i][0] + bias, acc[i][1] + bias,
                               acc[i][2] + bias, acc[i][3] + bias);
        *(float4*)(g_v + ((size_t)b * CH + d) * N_PIX + n0 + tx * 4) = o;
    }
}

// ================== kernel 3: energy E = Q K^T (K=32), f32x2 inner ================
__global__ void __launch_bounds__(256) energy_kernel()
{
    __shared__ u64   sQ2[32][68];  // [d][n], each entry = {q,q} duplicated
    __shared__ float sKf[32][68];  // [d][m]

    int b  = blockIdx.z;
    int n0 = blockIdx.y * 64;
    int m0 = blockIdx.x * 64;
    int tx = threadIdx.x, ty = threadIdx.y, tid = ty * 16 + tx;

    const float* qb = g_q + ((size_t)b * N_PIX + n0) * DQK;
    const float* kb = g_k + ((size_t)b * N_PIX + m0) * DQK;

    for (int idx = tid; idx < 512; idx += 256) {
        int r = idx >> 3, c4 = idx & 7;
        float4 q4 = *(const float4*)(qb + (size_t)r * DQK + c4 * 4);
        sQ2[c4 * 4 + 0][r] = pack2(q4.x, q4.x);
        sQ2[c4 * 4 + 1][r] = pack2(q4.y, q4.y);
        sQ2[c4 * 4 + 2][r] = pack2(q4.z, q4.z);
        sQ2[c4 * 4 + 3][r] = pack2(q4.w, q4.w);
        float4 k4 = *(const float4*)(kb + (size_t)r * DQK + c4 * 4);
        sKf[c4 * 4 + 0][r] = k4.x; sKf[c4 * 4 + 1][r] = k4.y;
        sKf[c4 * 4 + 2][r] = k4.z; sKf[c4 * 4 + 3][r] = k4.w;
    }
    __syncthreads();

    u64 acc[4][2] = {};
#pragma unroll
    for (int k = 0; k < 32; k++) {
        ulonglong2 a01 = *(const ulonglong2*)&sQ2[k][ty * 4];
        ulonglong2 a23 = *(const ulonglong2*)&sQ2[k][ty * 4 + 2];
        ulonglong2 bb  = *(const ulonglong2*)&sKf[k][tx * 4];
        u64 aa[4] = {a01.x, a01.y, a23.x, a23.y};
#pragma unroll
        for (int i = 0; i < 4; i++) {
            acc[i][0] = fma2(aa[i], bb.x, acc[i][0]);
            acc[i][1] = fma2(aa[i], bb.y, acc[i][1]);
        }
    }

    float* pout = g_p + ((size_t)b * N_PIX + n0 + ty * 4) * N_PIX + m0 + tx * 4;
#pragma unroll
    for (int i = 0; i < 4; i++) {
        float2 e01 = unpack2(acc[i][0]);
        float2 e23 = unpack2(acc[i][1]);
        *(float4*)(pout + (size_t)i * N_PIX) = make_float4(e01.x, e01.y, e23.x, e23.y);
    }
}

// ================== kernel 4: row softmax over m (in place on g_p) =================
__global__ void __launch_bounds__(256) softmax_kernel()
{
    size_t row = (size_t)blockIdx.y * N_PIX + blockIdx.x;
    float* p = g_p + row * N_PIX;
    int t = threadIdx.x;

    float v[16];
#pragma unroll
    for (int c = 0; c < 4; c++) {
        float4 f = *(const float4*)(p + c * 1024 + t * 4);
        v[c * 4 + 0] = f.x; v[c * 4 + 1] = f.y; v[c * 4 + 2] = f.z; v[c * 4 + 3] = f.w;
    }

    float mx = v[0];
#pragma unroll
    for (int i = 1; i < 16; i++) mx = fmaxf(mx, v[i]);

    __shared__ float sred[8];
    __shared__ float sbc;
#pragma unroll
    for (int o = 16; o > 0; o >>= 1) mx = fmaxf(mx, __shfl_xor_sync(0xffffffffu, mx, o));
    if ((t & 31) == 0) sred[t >> 5] = mx;
    __syncthreads();
    if (t == 0) {
        float m = sred[0];
#pragma unroll
        for (int i = 1; i < 8; i++) m = fmaxf(m, sred[i]);
        sbc = m;
    }
    __syncthreads();
    mx = sbc;

    float s = 0.f;
#pragma unroll
    for (int i = 0; i < 16; i++) { v[i] = __expf(v[i] - mx); s += v[i]; }
#pragma unroll
    for (int o = 16; o > 0; o >>= 1) s += __shfl_xor_sync(0xffffffffu, s, o);
    if ((t & 31) == 0) sred[t >> 5] = s;
    __syncthreads();
    __shared__ float ssum;
    if (t == 0) {
        float ss = 0.f;
#pragma unroll
        for (int i = 0; i < 8; i++) ss += sred[i];
        ssum = ss;
    }
    __syncthreads();
    float inv = 1.0f / ssum;

#pragma unroll
    for (int c = 0; c < 4; c++) {
        float4 f = make_float4(v[c * 4 + 0] * inv, v[c * 4 + 1] * inv,
                               v[c * 4 + 2] * inv, v[c * 4 + 3] * inv);
        *(float4*)(p + c * 1024 + t * 4) = f;
    }
}

// ================== kernel 5: out = V @ P^T + x  (the big one, f32x2) ==============
// out[b,d,n] = sum_m V[b,d,m] * P[b,n,m] + x[b,d,n]
__global__ void __launch_bounds__(256, 2) pv_kernel(
    const float* __restrict__ x, float* __restrict__ out)
{
    __shared__ u64   sV2[16][130]; // [m][d], entries duplicated {v,v}
    __shared__ float sPf[16][132]; // [m][n]

    int b  = blockIdx.z;
    int d0 = blockIdx.y * 128;
    int n0 = blockIdx.x * 128;
    int tx = threadIdx.x, ty = threadIdx.y, tid = ty * 16 + tx;

    const float* Vb = g_v + ((size_t)b * CH + d0) * N_PIX;
    const float* Pb = g_p + ((size_t)b * N_PIX + n0) * N_PIX;

    u64 acc[8][4] = {};

    for (int m0 = 0; m0 < N_PIX; m0 += 16) {
#pragma unroll
        for (int it = 0; it < 2; it++) {
            int idx = tid + it * 256;           // 0..511
            int r = idx >> 2, q = idx & 3;      // r = row (0..127), q = m/4 (0..3)
            float4 v4 = *(const float4*)(Vb + (size_t)r * N_PIX + m0 + q * 4);
            sV2[q * 4 + 0][r] = pack2(v4.x, v4.x);
            sV2[q * 4 + 1][r] = pack2(v4.y, v4.y);
            sV2[q * 4 + 2][r] = pack2(v4.z, v4.z);
            sV2[q * 4 + 3][r] = pack2(v4.w, v4.w);
            float4 p4 = *(const float4*)(Pb + (size_t)r * N_PIX + m0 + q * 4);
            sPf[q * 4 + 0][r] = p4.x; sPf[q * 4 + 1][r] = p4.y;
            sPf[q * 4 + 2][r] = p4.z; sPf[q * 4 + 3][r] = p4.w;
        }
        __syncthreads();

#pragma unroll
        for (int k = 0; k < 16; k++) {
            ulonglong2 a01 = *(const ulonglong2*)&sV2[k][ty * 8];
            ulonglong2 a23 = *(const ulonglong2*)&sV2[k][ty * 8 + 2];
            ulonglong2 a45 = *(const ulonglong2*)&sV2[k][ty * 8 + 4];
            ulonglong2 a67 = *(const ulonglong2*)&sV2[k][ty * 8 + 6];
            ulonglong2 b01 = *(const ulonglong2*)&sPf[k][tx * 8];
            ulonglong2 b23 = *(const ulonglong2*)&sPf[k][tx * 8 + 4];
            u64 aa[8] = {a01.x, a01.y, a23.x, a23.y, a45.x, a45.y, a67.x, a67.y};
            u64 bb[4] = {b01.x, b01.y, b23.x, b23.y};
#pragma unroll
            for (int i = 0; i < 8; i++)
#pragma unroll
                for (int j = 0; j < 4; j++)
                    acc[i][j] = fma2(aa[i], bb[j], acc[i][j]);
        }
        __syncthreads();
    }

    size_t obase = ((size_t)b * CH + d0 + ty * 8) * N_PIX + n0 + tx * 8;
#pragma unroll
    for (int i = 0; i < 8; i++) {
        const float* xr  = x   + obase + (size_t)i * N_PIX;
        float*       orr = out + obase + (size_t)i * N_PIX;
        float2 f0 = unpack2(acc[i][0]);
        float2 f1 = unpack2(acc[i][1]);
        float2 f2 = unpack2(acc[i][2]);
        float2 f3 = unpack2(acc[i][3]);
        float4 x0 = *(const float4*)(xr);
        float4 x1 = *(const float4*)(xr + 4);
        *(float4*)(orr)     = make_float4(f0.x + x0.x, f0.y + x0.y, f1.x + x0.z, f1.y + x0.w);
        *(float4*)(orr + 4) = make_float4(f2.x + x1.x, f2.y + x1.y, f3.x + x1.z, f3.y + x1.w);
    }
}

// ================== launch =========================================================
extern "C" void kernel_launch(void* const* d_in, const int* in_sizes, int n_in,
                              void* d_out, int out_size)
{
    (void)in_sizes; (void)n_in; (void)out_size;
    const float* x  = (const float*)d_in[0];
    const float* Wq = (const float*)d_in[1];
    const float* bq = (const float*)d_in[2];
    const float* Wk = (const float*)d_in[3];
    const float* bk = (const float*)d_in[4];
    const float* Wv = (const float*)d_in[5];
    const float* bv = (const float*)d_in[6];
    float* out = (float*)d_out;

    dim3 blk2(16, 16);
    proj_qk_kernel<<<dim3(16, 4), 256>>>(x, Wq, bq, Wk, bk);
    proj_v_kernel<<<dim3(64, 4, 4), blk2>>>(x, Wv, bv);
    energy_kernel<<<dim3(64, 64, 4), blk2>>>();
    softmax_kernel<<<dim3(4096, 4), 256>>>();
    pv_kernel<<<dim3(32, 2, 4), blk2>>>(x, out);
}

// round 4
// speedup vs baseline: 2.0109x; 2.0109x over previous
#include <cuda_runtime.h>
#include <cuda_bf16.h>
#include <cstdint>

#define N_PIX 4096
#define BATCH 4
#define CH    256
#define DQK   32

typedef unsigned long long u64;
typedef unsigned int u32;

// ---------------- scratch (device globals; no allocation in kernel_launch) ---------
__device__ float g_q[(size_t)BATCH * N_PIX * DQK];   // [b][n][d]   2 MB
__device__ float g_k[(size_t)BATCH * N_PIX * DQK];   // [b][m][d]   2 MB
__device__ float g_p[(size_t)BATCH * N_PIX * N_PIX]; // [b][n][m] 256 MB (energy, fp32)
__device__ __nv_bfloat16 g_vh[(size_t)BATCH * CH * N_PIX];      // V hi  8 MB
__device__ __nv_bfloat16 g_vl[(size_t)BATCH * CH * N_PIX];      // V lo  8 MB
__device__ __nv_bfloat16 g_ph[(size_t)BATCH * N_PIX * N_PIX];   // P hi 128 MB
__device__ __nv_bfloat16 g_pl[(size_t)BATCH * N_PIX * N_PIX];   // P lo 128 MB

// ---------------- f32x2 helpers (used by energy kernel) ----------------------------
__device__ __forceinline__ u64 fma2(u64 a, u64 b, u64 c) {
    u64 d;
    asm("fma.rn.f32x2 %0, %1, %2, %3;" : "=l"(d) : "l"(a), "l"(b), "l"(c));
    return d;
}
__device__ __forceinline__ u64 pack2(float x, float y) {
    u64 r;
    asm("mov.b64 %0, {%1, %2};" : "=l"(r) : "f"(x), "f"(y));
    return r;
}
__device__ __forceinline__ float2 unpack2(u64 v) {
    float2 r;
    asm("mov.b64 {%0, %1}, %2;" : "=f"(r.x), "=f"(r.y) : "l"(v));
    return r;
}

// ---------------- split-bf16 store helper ------------------------------------------
__device__ __forceinline__ void split_store4(__nv_bfloat16* hp, __nv_bfloat16* lp,
                                             float f0, float f1, float f2, float f3)
{
    __nv_bfloat16 h0 = __float2bfloat16(f0), h1 = __float2bfloat16(f1);
    __nv_bfloat16 h2 = __float2bfloat16(f2), h3 = __float2bfloat16(f3);
    __nv_bfloat16 l0 = __float2bfloat16(f0 - __bfloat162float(h0));
    __nv_bfloat16 l1 = __float2bfloat16(f1 - __bfloat162float(h1));
    __nv_bfloat16 l2 = __float2bfloat16(f2 - __bfloat162float(h2));
    __nv_bfloat16 l3 = __float2bfloat16(f3 - __bfloat162float(h3));
    __nv_bfloat162 a, b, c, d;
    a.x = h0; a.y = h1; b.x = h2; b.y = h3;
    c.x = l0; c.y = l1; d.x = l2; d.y = l3;
    uint2 uh, ul;
    uh.x = *(const unsigned int*)&a; uh.y = *(const unsigned int*)&b;
    ul.x = *(const unsigned int*)&c; ul.y = *(const unsigned int*)&d;
    *(uint2*)hp = uh;
    *(uint2*)lp = ul;
}

// ---------------- smem / cp.async helpers -------------------------------------------
__device__ __forceinline__ u32 smem_u32(const void* p) {
    u32 a;
    asm("{ .reg .u64 t; cvta.to.shared.u64 t, %1; cvt.u32.u64 %0, t; }" : "=r"(a) : "l"(p));
    return a;
}
__device__ __forceinline__ void cp16(u32 d, const void* s) {
    asm volatile("cp.async.cg.shared.global [%0], [%1], 16;" :: "r"(d), "l"(s));
}
#define CP_COMMIT() asm volatile("cp.async.commit_group;" ::: "memory")
#define CP_WAIT1()  asm volatile("cp.async.wait_group 1;" ::: "memory")
#define CP_WAIT0()  asm volatile("cp.async.wait_group 0;" ::: "memory")

__device__ __forceinline__ void ldm4(u32 addr, u32& r0, u32& r1, u32& r2, u32& r3) {
    asm volatile("ldmatrix.sync.aligned.m8n8.x4.shared.b16 {%0,%1,%2,%3}, [%4];"
                 : "=r"(r0), "=r"(r1), "=r"(r2), "=r"(r3) : "r"(addr));
}
__device__ __forceinline__ void mma16816(float* c, const u32* a, u32 b0, u32 b1) {
    asm volatile(
        "mma.sync.aligned.m16n8k16.row.col.f32.bf16.bf16.f32 "
        "{%0,%1,%2,%3}, {%4,%5,%6,%7}, {%8,%9}, {%0,%1,%2,%3};"
        : "+f"(c[0]), "+f"(c[1]), "+f"(c[2]), "+f"(c[3])
        : "r"(a[0]), "r"(a[1]), "r"(a[2]), "r"(a[3]), "r"(b0), "r"(b1));
}

// ================== kernel 1: q/k projection =======================================
__global__ void __launch_bounds__(256) proj_qk_kernel(
    const float* __restrict__ x,
    const float* __restrict__ Wq, const float* __restrict__ bq,
    const float* __restrict__ Wk, const float* __restrict__ bk)
{
    __shared__ float sWq[32 * 128];
    __shared__ float sWk[32 * 128];

    int b = blockIdx.y;
    int n = blockIdx.x * 256 + threadIdx.x;

    float qa[32], ka[32];
#pragma unroll
    for (int d = 0; d < 32; d++) { qa[d] = 0.f; ka[d] = 0.f; }

    const float* xb = x + (size_t)b * CH * N_PIX + n;

    for (int ch = 0; ch < 2; ch++) {
        for (int i = threadIdx.x; i < 32 * 128; i += 256) {
            int d = i >> 7, c = i & 127;
            sWq[i] = Wq[d * CH + ch * 128 + c];
            sWk[i] = Wk[d * CH + ch * 128 + c];
        }
        __syncthreads();

        const float* xc = xb + (size_t)ch * 128 * N_PIX;
        for (int c = 0; c < 128; c += 4) {
            float x0 = xc[(size_t)(c + 0) * N_PIX];
            float x1 = xc[(size_t)(c + 1) * N_PIX];
            float x2 = xc[(size_t)(c + 2) * N_PIX];
            float x3 = xc[(size_t)(c + 3) * N_PIX];
#pragma unroll
            for (int d = 0; d < 32; d++) {
                float4 wq = *(const float4*)&sWq[d * 128 + c];
                qa[d] += wq.x * x0; qa[d] += wq.y * x1;
                qa[d] += wq.z * x2; qa[d] += wq.w * x3;
                float4 wk = *(const float4*)&sWk[d * 128 + c];
                ka[d] += wk.x * x0; ka[d] += wk.y * x1;
                ka[d] += wk.z * x2; ka[d] += wk.w * x3;
            }
        }
        __syncthreads();
    }

    float* qo = g_q + ((size_t)b * N_PIX + n) * DQK;
    float* ko = g_k + ((size_t)b * N_PIX + n) * DQK;
#pragma unroll
    for (int d = 0; d < 32; d += 4) {
        *(float4*)(qo + d) = make_float4(qa[d] + bq[d], qa[d + 1] + bq[d + 1],
                                         qa[d + 2] + bq[d + 2], qa[d + 3] + bq[d + 3]);
        *(float4*)(ko + d) = make_float4(ka[d] + bk[d], ka[d + 1] + bk[d + 1],
                                         ka[d + 2] + bk[d + 2], ka[d + 3] + bk[d + 3]);
    }
}

// ================== kernel 2: v projection (writes split-bf16 V) ===================
__global__ void __launch_bounds__(256) proj_v_kernel(
    const float* __restrict__ x, const float* __restrict__ Wv, const float* __restrict__ bv)
{
    __shared__ float sA[32][68];  // [c][d]  (Wv transposed)
    __shared__ float sB[32][68];  // [c][n]

    int b  = blockIdx.z;
    int n0 = blockIdx.x * 64;
    int d0 = blockIdx.y * 64;
    int tx = threadIdx.x, ty = threadIdx.y, tid = ty * 16 + tx;

    float acc[4][4] = {};

    for (int c0 = 0; c0 < CH; c0 += 32) {
        for (int idx = tid; idx < 512; idx += 256) {
            int r = idx >> 3, q = idx & 7;
            float4 w = *(const float4*)(Wv + (size_t)(d0 + r) * CH + c0 + q * 4);
            sA[q * 4 + 0][r] = w.x; sA[q * 4 + 1][r] = w.y;
            sA[q * 4 + 2][r] = w.z; sA[q * 4 + 3][r] = w.w;

            int r2 = idx >> 4, q2 = idx & 15;
            float4 xv = *(const float4*)(x + ((size_t)b * CH + c0 + r2) * N_PIX + n0 + q2 * 4);
            *(float4*)&sB[r2][q2 * 4] = xv;
        }
        __syncthreads();

#pragma unroll
        for (int k = 0; k < 32; k++) {
            float4 a4 = *(const float4*)&sA[k][ty * 4];
            float4 b4 = *(const float4*)&sB[k][tx * 4];
            float av[4] = {a4.x, a4.y, a4.z, a4.w};
            float bw[4] = {b4.x, b4.y, b4.z, b4.w};
#pragma unroll
            for (int i = 0; i < 4; i++)
#pragma unroll
                for (int j = 0; j < 4; j++)
                    acc[i][j] += av[i] * bw[j];
        }
        __syncthreads();
    }

#pragma unroll
    for (int i = 0; i < 4; i++) {
        int d = d0 + ty * 4 + i;
        float bias = bv[d];
        size_t base = ((size_t)b * CH + d) * N_PIX + n0 + tx * 4;
        split_store4(g_vh + base, g_vl + base,
                     acc[i][0] + bias, acc[i][1] + bias,
                     acc[i][2] + bias, acc[i][3] + bias);
    }
}

// ================== kernel 3: energy E = Q K^T (K=32), f32x2 inner ================
__global__ void __launch_bounds__(256) energy_kernel()
{
    __shared__ u64   sQ2[32][68];
    __shared__ float sKf[32][68];

    int b  = blockIdx.z;
    int n0 = blockIdx.y * 64;
    int m0 = blockIdx.x * 64;
    int tx = threadIdx.x, ty = threadIdx.y, tid = ty * 16 + tx;

    const float* qb = g_q + ((size_t)b * N_PIX + n0) * DQK;
    const float* kb = g_k + ((size_t)b * N_PIX + m0) * DQK;

    for (int idx = tid; idx < 512; idx += 256) {
        int r = idx >> 3, c4 = idx & 7;
        float4 q4 = *(const float4*)(qb + (size_t)r * DQK + c4 * 4);
        sQ2[c4 * 4 + 0][r] = pack2(q4.x, q4.x);
        sQ2[c4 * 4 + 1][r] = pack2(q4.y, q4.y);
        sQ2[c4 * 4 + 2][r] = pack2(q4.z, q4.z);
        sQ2[c4 * 4 + 3][r] = pack2(q4.w, q4.w);
        float4 k4 = *(const float4*)(kb + (size_t)r * DQK + c4 * 4);
        sKf[c4 * 4 + 0][r] = k4.x; sKf[c4 * 4 + 1][r] = k4.y;
        sKf[c4 * 4 + 2][r] = k4.z; sKf[c4 * 4 + 3][r] = k4.w;
    }
    __syncthreads();

    u64 acc[4][2] = {};
#pragma unroll
    for (int k = 0; k < 32; k++) {
        ulonglong2 a01 = *(const ulonglong2*)&sQ2[k][ty * 4];
        ulonglong2 a23 = *(const ulonglong2*)&sQ2[k][ty * 4 + 2];
        ulonglong2 bb  = *(const ulonglong2*)&sKf[k][tx * 4];
        u64 aa[4] = {a01.x, a01.y, a23.x, a23.y};
#pragma unroll
        for (int i = 0; i < 4; i++) {
            acc[i][0] = fma2(aa[i], bb.x, acc[i][0]);
            acc[i][1] = fma2(aa[i], bb.y, acc[i][1]);
        }
    }

    float* pout = g_p + ((size_t)b * N_PIX + n0 + ty * 4) * N_PIX + m0 + tx * 4;
#pragma unroll
    for (int i = 0; i < 4; i++) {
        float2 e01 = unpack2(acc[i][0]);
        float2 e23 = unpack2(acc[i][1]);
        *(float4*)(pout + (size_t)i * N_PIX) = make_float4(e01.x, e01.y, e23.x, e23.y);
    }
}

// ================== kernel 4: row softmax, emits split-bf16 P ======================
__global__ void __launch_bounds__(256) softmax_kernel()
{
    size_t row = (size_t)blockIdx.y * N_PIX + blockIdx.x;
    const float* p = g_p + row * N_PIX;
    int t = threadIdx.x;

    float v[16];
#pragma unroll
    for (int c = 0; c < 4; c++) {
        float4 f = *(const float4*)(p + c * 1024 + t * 4);
        v[c * 4 + 0] = f.x; v[c * 4 + 1] = f.y; v[c * 4 + 2] = f.z; v[c * 4 + 3] = f.w;
    }

    float mx = v[0];
#pragma unroll
    for (int i = 1; i < 16; i++) mx = fmaxf(mx, v[i]);

    __shared__ float sred[8];
    __shared__ float sbc;
#pragma unroll
    for (int o = 16; o > 0; o >>= 1) mx = fmaxf(mx, __shfl_xor_sync(0xffffffffu, mx, o));
    if ((t & 31) == 0) sred[t >> 5] = mx;
    __syncthreads();
    if (t == 0) {
        float m = sred[0];
#pragma unroll
        for (int i = 1; i < 8; i++) m = fmaxf(m, sred[i]);
        sbc = m;
    }
    __syncthreads();
    mx = sbc;

    float s = 0.f;
#pragma unroll
    for (int i = 0; i < 16; i++) { v[i] = __expf(v[i] - mx); s += v[i]; }
#pragma unroll
    for (int o = 16; o > 0; o >>= 1) s += __shfl_xor_sync(0xffffffffu, s, o);
    if ((t & 31) == 0) sred[t >> 5] = s;
    __syncthreads();
    __shared__ float ssum;
    if (t == 0) {
        float ss = 0.f;
#pragma unroll
        for (int i = 0; i < 8; i++) ss += sred[i];
        ssum = ss;
    }
    __syncthreads();
    float inv = 1.0f / ssum;

    __nv_bfloat16* hp = g_ph + row * N_PIX;
    __nv_bfloat16* lp = g_pl + row * N_PIX;
#pragma unroll
    for (int c = 0; c < 4; c++) {
        int col = c * 1024 + t * 4;
        split_store4(hp + col, lp + col,
                     v[c * 4 + 0] * inv, v[c * 4 + 1] * inv,
                     v[c * 4 + 2] * inv, v[c * 4 + 3] * inv);
    }
}

// ================== kernel 5: PV via mma.sync bf16 (split hi/lo, 3-MMA) ============
// out[b, d0+0..127, n0+0..127] = sum_m V[d,m] * P[n,m] + x
// CTA tile 128x128, K chunk 32, double-buffered cp.async.
// SMEM per stage: 4 matrices x 128 rows x 40 halves (32 data + 8 pad) = 40960 B.
#define PV_ROWPAD 40
#define PV_MAT_HALVES (128 * PV_ROWPAD)          // 5120
#define PV_STAGE_HALVES (4 * PV_MAT_HALVES)      // 20480
#define PV_SMEM_BYTES (2 * PV_STAGE_HALVES * 2)  // 81920

__global__ void __launch_bounds__(256, 2) pv_mma_kernel(
    const float* __restrict__ x, float* __restrict__ out)
{
    extern __shared__ __nv_bfloat16 sm[];
    const u32 sbase = smem_u32(sm);

    const int tid  = threadIdx.x;
    const int wid  = tid >> 5, lane = tid & 31;
    const int wm   = wid >> 1;          // 0..3  (d direction, 32 rows each)
    const int wn   = wid & 1;           // 0..1  (n direction, 64 cols each)
    const int b    = blockIdx.z;
    const int d0   = blockIdx.y * 128;
    const int n0   = blockIdx.x * 128;

    const __nv_bfloat16* vh = g_vh + ((size_t)b * CH + d0) * N_PIX;
    const __nv_bfloat16* vl = g_vl + ((size_t)b * CH + d0) * N_PIX;
    const __nv_bfloat16* ph = g_ph + ((size_t)b * N_PIX + n0) * N_PIX;
    const __nv_bfloat16* pl = g_pl + ((size_t)b * N_PIX + n0) * N_PIX;

    float acc[2][8][4];
#pragma unroll
    for (int i = 0; i < 2; i++)
#pragma unroll
        for (int j = 0; j < 8; j++)
#pragma unroll
            for (int q = 0; q < 4; q++) acc[i][j][q] = 0.f;

    // ldmatrix source addresses (byte offsets within a stage)
    // A (V): rows = d, 16x16 tiles: lanes 0-15 rows, lanes 16-31 same rows col+8
    const int a_row = wm * 32 + (lane & 15);
    const int a_col = (lane >> 4) << 3;
    // B (P): lanes 0-7: n 0-7 k0; 8-15: n 0-7 k8; 16-23: n 8-15 k0; 24-31: n 8-15 k8
    const int b_row = wn * 64 + (lane & 7) + ((lane >> 4) & 1) * 8;
    const int b_col = ((lane >> 3) & 1) * 8;

    auto load_stage = [&](int stg, int m0) {
#pragma unroll
        for (int j = 0; j < 8; ++j) {
            int idx = tid + j * 256;          // 0..2047
            int mat = idx >> 9;               // 0..3
            int within = idx & 511;
            int row = within >> 2;            // 0..127
            int c4 = within & 3;              // 16B chunk
            const __nv_bfloat16* src =
                (mat == 0 ? vh : mat == 1 ? vl : mat == 2 ? ph : pl)
                + (size_t)row * N_PIX + m0 + c4 * 8;
            u32 dst = sbase + (u32)(stg * PV_STAGE_HALVES + mat * PV_MAT_HALVES
                                    + row * PV_ROWPAD + c4 * 8) * 2;
            cp16(dst, src);
        }
    };

    load_stage(0, 0);
    CP_COMMIT();

    const int NSTG = N_PIX / 32;   // 128
    for (int s = 0; s < NSTG; ++s) {
        if (s + 1 < NSTG) {
            load_stage((s + 1) & 1, (s + 1) * 32);
            CP_COMMIT();
            CP_WAIT1();
        } else {
            CP_WAIT0();
        }
        __syncthreads();

        const u32 stgb = sbase + (u32)((s & 1) * PV_STAGE_HALVES) * 2;
        const u32 ah_b = stgb;
        const u32 al_b = stgb + PV_MAT_HALVES * 2;
        const u32 bh_b = stgb + 2 * PV_MAT_HALVES * 2;
        const u32 bl_b = stgb + 3 * PV_MAT_HALVES * 2;

#pragma unroll
        for (int kk = 0; kk < 32; kk += 16) {
            u32 ah[2][4], al[2][4];
#pragma unroll
            for (int mf = 0; mf < 2; mf++) {
                u32 ao = (u32)((a_row + mf * 16) * PV_ROWPAD + a_col + kk) * 2;
                ldm4(ah_b + ao, ah[mf][0], ah[mf][1], ah[mf][2], ah[mf][3]);
                ldm4(al_b + ao, al[mf][0], al[mf][1], al[mf][2], al[mf][3]);
            }
#pragma unroll
            for (int nf2 = 0; nf2 < 4; nf2++) {
                u32 bo = (u32)((b_row + nf2 * 16) * PV_ROWPAD + b_col + kk) * 2;
                u32 bh[4], bl[4];
                ldm4(bh_b + bo, bh[0], bh[1], bh[2], bh[3]);
                ldm4(bl_b + bo, bl[0], bl[1], bl[2], bl[3]);
#pragma unroll
                for (int mf = 0; mf < 2; mf++) {
                    // n-frag 2*nf2 : b regs {0,1}; n-frag 2*nf2+1 : {2,3}
                    mma16816(acc[mf][nf2 * 2],     ah[mf], bh[0], bh[1]);
                    mma16816(acc[mf][nf2 * 2],     ah[mf], bl[0], bl[1]);
                    mma16816(acc[mf][nf2 * 2],     al[mf], bh[0], bh[1]);
                    mma16816(acc[mf][nf2 * 2 + 1], ah[mf], bh[2], bh[3]);
                    mma16816(acc[mf][nf2 * 2 + 1], ah[mf], bl[2], bl[3]);
                    mma16816(acc[mf][nf2 * 2 + 1], al[mf], bh[2], bh[3]);
                }
            }
        }
        __syncthreads();
    }

    // epilogue: acc layout per mma: c0,c1 -> row lane>>2, cols 2*(lane&3)+{0,1};
    //           c2,c3 -> row (lane>>2)+8
    const int er = lane >> 2;
    const int ec = 2 * (lane & 3);
#pragma unroll
    for (int mf = 0; mf < 2; mf++) {
        const int d = d0 + wm * 32 + mf * 16 + er;
#pragma unroll
        for (int nf = 0; nf < 8; nf++) {
            const int n = n0 + wn * 64 + nf * 8 + ec;
            size_t o1 = ((size_t)b * CH + d) * N_PIX + n;
            size_t o2 = o1 + (size_t)8 * N_PIX;
            float2 x1 = *(const float2*)(x + o1);
            float2 x2 = *(const float2*)(x + o2);
            float2 r1 = make_float2(acc[mf][nf][0] + x1.x, acc[mf][nf][1] + x1.y);
            float2 r2 = make_float2(acc[mf][nf][2] + x2.x, acc[mf][nf][3] + x2.y);
            *(float2*)(out + o1) = r1;
            *(float2*)(out + o2) = r2;
        }
    }
}

// ================== launch =========================================================
extern "C" void kernel_launch(void* const* d_in, const int* in_sizes, int n_in,
                              void* d_out, int out_size)
{
    (void)in_sizes; (void)n_in; (void)out_size;
    const float* x  = (const float*)d_in[0];
    const float* Wq = (const float*)d_in[1];
    const float* bq = (const float*)d_in[2];
    const float* Wk = (const float*)d_in[3];
    const float* bk = (const float*)d_in[4];
    const float* Wv = (const float*)d_in[5];
    const float* bv = (const float*)d_in[6];
    float* out = (float*)d_out;

    static int smem_set = 0;
    if (!smem_set) {
        cudaFuncSetAttribute(pv_mma_kernel,
                             cudaFuncAttributeMaxDynamicSharedMemorySize, PV_SMEM_BYTES);
        smem_set = 1;
    }

    dim3 blk2(16, 16);
    proj_qk_kernel<<<dim3(16, 4), 256>>>(x, Wq, bq, Wk, bk);
    proj_v_kernel<<<dim3(64, 4, 4), blk2>>>(x, Wv, bv);
    energy_kernel<<<dim3(64, 64, 4), blk2>>>();
    softmax_kernel<<<dim3(4096, 4), 256>>>();
    pv_mma_kernel<<<dim3(32, 2, 4), 256, PV_SMEM_BYTES>>>(x, out);
}

// round 5
// speedup vs baseline: 2.3430x; 1.1652x over previous
#include <cuda_runtime.h>
#include <cuda_bf16.h>
#include <cstdint>

#define N_PIX 4096
#define BATCH 4
#define CH    256
#define DQK   32

typedef unsigned long long u64;
typedef unsigned int u32;

// ---------------- scratch (device globals; no allocation in kernel_launch) ---------
__device__ float g_q[(size_t)BATCH * N_PIX * DQK];   // [b][n][d]   2 MB
__device__ float g_k[(size_t)BATCH * N_PIX * DQK];   // [b][m][d]   2 MB
__device__ __nv_bfloat16 g_vh[(size_t)BATCH * CH * N_PIX];      // V hi  8 MB
__device__ __nv_bfloat16 g_vl[(size_t)BATCH * CH * N_PIX];      // V lo  8 MB
__device__ __nv_bfloat16 g_ph[(size_t)BATCH * N_PIX * N_PIX];   // P hi (unnormalized) 128 MB
__device__ __nv_bfloat16 g_pl[(size_t)BATCH * N_PIX * N_PIX];   // P lo 128 MB
__device__ float g_psum[(size_t)BATCH * 64 * N_PIX]; // partial row sums  4 MB
__device__ float g_rinv[(size_t)BATCH * N_PIX];      // 1/rowsum        64 KB

// ---------------- f32x2 helpers ------------------------------------------------------
__device__ __forceinline__ u64 fma2(u64 a, u64 b, u64 c) {
    u64 d;
    asm("fma.rn.f32x2 %0, %1, %2, %3;" : "=l"(d) : "l"(a), "l"(b), "l"(c));
    return d;
}
__device__ __forceinline__ u64 pack2(float x, float y) {
    u64 r;
    asm("mov.b64 %0, {%1, %2};" : "=l"(r) : "f"(x), "f"(y));
    return r;
}
__device__ __forceinline__ float2 unpack2(u64 v) {
    float2 r;
    asm("mov.b64 {%0, %1}, %2;" : "=f"(r.x), "=f"(r.y) : "l"(v));
    return r;
}

// ---------------- split-bf16 store helper ------------------------------------------
__device__ __forceinline__ void split_store4(__nv_bfloat16* hp, __nv_bfloat16* lp,
                                             float f0, float f1, float f2, float f3)
{
    __nv_bfloat16 h0 = __float2bfloat16(f0), h1 = __float2bfloat16(f1);
    __nv_bfloat16 h2 = __float2bfloat16(f2), h3 = __float2bfloat16(f3);
    __nv_bfloat16 l0 = __float2bfloat16(f0 - __bfloat162float(h0));
    __nv_bfloat16 l1 = __float2bfloat16(f1 - __bfloat162float(h1));
    __nv_bfloat16 l2 = __float2bfloat16(f2 - __bfloat162float(h2));
    __nv_bfloat16 l3 = __float2bfloat16(f3 - __bfloat162float(h3));
    __nv_bfloat162 a, b, c, d;
    a.x = h0; a.y = h1; b.x = h2; b.y = h3;
    c.x = l0; c.y = l1; d.x = l2; d.y = l3;
    uint2 uh, ul;
    uh.x = *(const unsigned int*)&a; uh.y = *(const unsigned int*)&b;
    ul.x = *(const unsigned int*)&c; ul.y = *(const unsigned int*)&d;
    *(uint2*)hp = uh;
    *(uint2*)lp = ul;
}

// ---------------- smem / cp.async / mma helpers -------------------------------------
__device__ __forceinline__ u32 smem_u32(const void* p) {
    u32 a;
    asm("{ .reg .u64 t; cvta.to.shared.u64 t, %1; cvt.u32.u64 %0, t; }" : "=r"(a) : "l"(p));
    return a;
}
__device__ __forceinline__ void cp16(u32 d, const void* s) {
    asm volatile("cp.async.cg.shared.global [%0], [%1], 16;" :: "r"(d), "l"(s));
}
#define CP_COMMIT() asm volatile("cp.async.commit_group;" ::: "memory")
#define CP_WAIT1()  asm volatile("cp.async.wait_group 1;" ::: "memory")
#define CP_WAIT0()  asm volatile("cp.async.wait_group 0;" ::: "memory")

__device__ __forceinline__ void ldm4(u32 addr, u32& r0, u32& r1, u32& r2, u32& r3) {
    asm volatile("ldmatrix.sync.aligned.m8n8.x4.shared.b16 {%0,%1,%2,%3}, [%4];"
                 : "=r"(r0), "=r"(r1), "=r"(r2), "=r"(r3) : "r"(addr));
}
__device__ __forceinline__ void mma16816(float* c, const u32* a, u32 b0, u32 b1) {
    asm volatile(
        "mma.sync.aligned.m16n8k16.row.col.f32.bf16.bf16.f32 "
        "{%0,%1,%2,%3}, {%4,%5,%6,%7}, {%8,%9}, {%0,%1,%2,%3};"
        : "+f"(c[0]), "+f"(c[1]), "+f"(c[2]), "+f"(c[3])
        : "r"(a[0]), "r"(a[1]), "r"(a[2]), "r"(a[3]), "r"(b0), "r"(b1));
}

// ================== kernel 1: q/k projection (register-blocked FFMA2) ==============
// Block: 256 pixels, all 64 outputs (32 q + 32 k). Thread: 8 d x 8 n.
__global__ void __launch_bounds__(256) proj_qk_kernel(
    const float* __restrict__ x,
    const float* __restrict__ Wq, const float* __restrict__ bq,
    const float* __restrict__ Wk, const float* __restrict__ bk)
{
    __shared__ float sX[32 * 260];   // [g][cc*8+j]
    __shared__ float sW[32 * 68];    // [cc][d]  d 0..31 = q, 32..63 = k

    const int tid = threadIdx.x;
    const int g = tid & 31;          // n-group (8 pixels)
    const int h = tid >> 5;          // 0..7 : h<4 -> q, else k
    const int b = blockIdx.y;
    const int n0 = blockIdx.x * 256;
    const bool isq = (h < 4);
    const int dbase = (h & 3) * 8;
    const int woff = (isq ? 0 : 32) + dbase;

    u64 acc[8][4];
#pragma unroll
    for (int i = 0; i < 8; i++)
#pragma unroll
        for (int p = 0; p < 4; p++) acc[i][p] = 0;

    for (int c0 = 0; c0 < CH; c0 += 32) {
        __syncthreads();
        // stage x: thread (g, cc = h + 8*pass)
#pragma unroll
        for (int pass = 0; pass < 4; ++pass) {
            int cc = h + pass * 8;
            const float* src = x + ((size_t)b * CH + c0 + cc) * N_PIX + n0 + g * 8;
            float4 v0 = *(const float4*)src;
            float4 v1 = *(const float4*)(src + 4);
            float* dst = sX + g * 260 + cc * 8;
            *(float4*)dst = v0;
            *(float4*)(dst + 4) = v1;
        }
        // stage W (transposed): thread: d = tid&31, c4 = (tid>>5)*4
        {
            int d = tid & 31;
            int c4 = (tid >> 5) * 4;
            float4 wq4 = *(const float4*)(Wq + d * CH + c0 + c4);
            float4 wk4 = *(const float4*)(Wk + d * CH + c0 + c4);
            sW[(c4 + 0) * 68 + d] = wq4.x; sW[(c4 + 1) * 68 + d] = wq4.y;
            sW[(c4 + 2) * 68 + d] = wq4.z; sW[(c4 + 3) * 68 + d] = wq4.w;
            sW[(c4 + 0) * 68 + 32 + d] = wk4.x; sW[(c4 + 1) * 68 + 32 + d] = wk4.y;
            sW[(c4 + 2) * 68 + 32 + d] = wk4.z; sW[(c4 + 3) * 68 + 32 + d] = wk4.w;
        }
        __syncthreads();

#pragma unroll 8
        for (int cc = 0; cc < 32; ++cc) {
            const float* xp = sX + g * 260 + cc * 8;
            float4 xa = *(const float4*)xp;
            float4 xb = *(const float4*)(xp + 4);
            u64 xpair[4] = {pack2(xa.x, xa.y), pack2(xa.z, xa.w),
                            pack2(xb.x, xb.y), pack2(xb.z, xb.w)};
            const float* wp = sW + cc * 68 + woff;
            float4 w0 = *(const float4*)wp;
            float4 w1 = *(const float4*)(wp + 4);
            float wv[8] = {w0.x, w0.y, w0.z, w0.w, w1.x, w1.y, w1.z, w1.w};
#pragma unroll
            for (int i = 0; i < 8; i++) {
                u64 wd = pack2(wv[i], wv[i]);
#pragma unroll
                for (int p = 0; p < 4; p++)
                    acc[i][p] = fma2(wd, xpair[p], acc[i][p]);
            }
        }
    }

    const float* bias = isq ? bq : bk;
    float bb[8];
#pragma unroll
    for (int i = 0; i < 8; i++) bb[i] = bias[dbase + i];
    float* outp = (isq ? g_q : g_k) + ((size_t)b * N_PIX + n0 + g * 8) * DQK + dbase;
#pragma unroll
    for (int j = 0; j < 8; j++) {     // pixel within group
        float v[8];
#pragma unroll
        for (int i = 0; i < 8; i++) {
            float2 t = unpack2(acc[i][j >> 1]);
            v[i] = (j & 1) ? t.y : t.x;
        }
        *(float4*)(outp + (size_t)j * DQK) =
            make_float4(v[0] + bb[0], v[1] + bb[1], v[2] + bb[2], v[3] + bb[3]);
        *(float4*)(outp + (size_t)j * DQK + 4) =
            make_float4(v[4] + bb[4], v[5] + bb[5], v[6] + bb[6], v[7] + bb[7]);
    }
}

// ================== kernel 2: v projection (writes split-bf16 V) ===================
__global__ void __launch_bounds__(256) proj_v_kernel(
    const float* __restrict__ x, const float* __restrict__ Wv, const float* __restrict__ bv)
{
    __shared__ float sA[32][68];  // [c][d]  (Wv transposed)
    __shared__ float sB[32][68];  // [c][n]

    int b  = blockIdx.z;
    int n0 = blockIdx.x * 64;
    int d0 = blockIdx.y * 64;
    int tx = threadIdx.x, ty = threadIdx.y, tid = ty * 16 + tx;

    float acc[4][4] = {};

    for (int c0 = 0; c0 < CH; c0 += 32) {
        for (int idx = tid; idx < 512; idx += 256) {
            int r = idx >> 3, q = idx & 7;
            float4 w = *(const float4*)(Wv + (size_t)(d0 + r) * CH + c0 + q * 4);
            sA[q * 4 + 0][r] = w.x; sA[q * 4 + 1][r] = w.y;
            sA[q * 4 + 2][r] = w.z; sA[q * 4 + 3][r] = w.w;

            int r2 = idx >> 4, q2 = idx & 15;
            float4 xv = *(const float4*)(x + ((size_t)b * CH + c0 + r2) * N_PIX + n0 + q2 * 4);
            *(float4*)&sB[r2][q2 * 4] = xv;
        }
        __syncthreads();

#pragma unroll
        for (int k = 0; k < 32; k++) {
            float4 a4 = *(const float4*)&sA[k][ty * 4];
            float4 b4 = *(const float4*)&sB[k][tx * 4];
            float av[4] = {a4.x, a4.y, a4.z, a4.w};
            float bw[4] = {b4.x, b4.y, b4.z, b4.w};
#pragma unroll
            for (int i = 0; i < 4; i++)
#pragma unroll
                for (int j = 0; j < 4; j++)
                    acc[i][j] += av[i] * bw[j];
        }
        __syncthreads();
    }

#pragma unroll
    for (int i = 0; i < 4; i++) {
        int d = d0 + ty * 4 + i;
        float bias = bv[d];
        size_t base = ((size_t)b * CH + d) * N_PIX + n0 + tx * 4;
        split_store4(g_vh + base, g_vl + base,
                     acc[i][0] + bias, acc[i][1] + bias,
                     acc[i][2] + bias, acc[i][3] + bias);
    }
}

// ================== kernel 3: fused energy + exp (unnormalized softmax) ============
// E = Q K^T (K=32); P_unnorm = exp(E) written split-bf16; partial row sums to g_psum.
__global__ void __launch_bounds__(256) energy_exp_kernel()
{
    __shared__ u64   sQ2[32][68];
    __shared__ float sKf[32][68];

    int b  = blockIdx.z;
    int n0 = blockIdx.y * 64;
    int m0 = blockIdx.x * 64;
    int tx = threadIdx.x, ty = threadIdx.y, tid = ty * 16 + tx;

    const float* qb = g_q + ((size_t)b * N_PIX + n0) * DQK;
    const float* kb = g_k + ((size_t)b * N_PIX + m0) * DQK;

    for (int idx = tid; idx < 512; idx += 256) {
        int r = idx >> 3, c4 = idx & 7;
        float4 q4 = *(const float4*)(qb + (size_t)r * DQK + c4 * 4);
        sQ2[c4 * 4 + 0][r] = pack2(q4.x, q4.x);
        sQ2[c4 * 4 + 1][r] = pack2(q4.y, q4.y);
        sQ2[c4 * 4 + 2][r] = pack2(q4.z, q4.z);
        sQ2[c4 * 4 + 3][r] = pack2(q4.w, q4.w);
        float4 k4 = *(const float4*)(kb + (size_t)r * DQK + c4 * 4);
        sKf[c4 * 4 + 0][r] = k4.x; sKf[c4 * 4 + 1][r] = k4.y;
        sKf[c4 * 4 + 2][r] = k4.z; sKf[c4 * 4 + 3][r] = k4.w;
    }
    __syncthreads();

    u64 acc[4][2] = {};
#pragma unroll
    for (int k = 0; k < 32; k++) {
        ulonglong2 a01 = *(const ulonglong2*)&sQ2[k][ty * 4];
        ulonglong2 a23 = *(const ulonglong2*)&sQ2[k][ty * 4 + 2];
        ulonglong2 bb  = *(const ulonglong2*)&sKf[k][tx * 4];
        u64 aa[4] = {a01.x, a01.y, a23.x, a23.y};
#pragma unroll
        for (int i = 0; i < 4; i++) {
            acc[i][0] = fma2(aa[i], bb.x, acc[i][0]);
            acc[i][1] = fma2(aa[i], bb.y, acc[i][1]);
        }
    }

    float rsv[4];
#pragma unroll
    for (int i = 0; i < 4; i++) {
        float2 e01 = unpack2(acc[i][0]);
        float2 e23 = unpack2(acc[i][1]);
        float e0 = __expf(e01.x), e1 = __expf(e01.y);
        float e2 = __expf(e23.x), e3 = __expf(e23.y);
        float rs = (e0 + e1) + (e2 + e3);
#pragma unroll
        for (int o = 1; o < 16; o <<= 1)
            rs += __shfl_xor_sync(0xffffffffu, rs, o);
        rsv[i] = rs;
        size_t off = ((size_t)b * N_PIX + n0 + ty * 4 + i) * N_PIX + m0 + tx * 4;
        split_store4(g_ph + off, g_pl + off, e0, e1, e2, e3);
    }
    if (tx == 0) {
        *(float4*)(g_psum + ((size_t)(b * 64 + blockIdx.x)) * N_PIX + n0 + ty * 4) =
            make_float4(rsv[0], rsv[1], rsv[2], rsv[3]);
    }
}

// ================== kernel 4: reduce partial sums -> 1/rowsum ======================
__global__ void __launch_bounds__(256) rsum_kernel()
{
    int idx = blockIdx.x * 256 + threadIdx.x;     // 0..16383
    int b = idx >> 12;
    int n = idx & 4095;
    float s = 0.f;
#pragma unroll 8
    for (int mt = 0; mt < 64; mt++)
        s += g_psum[((size_t)(b * 64 + mt)) * N_PIX + n];
    g_rinv[idx] = 1.0f / s;
}

// ================== kernel 5: PV via mma.sync bf16 (split hi/lo, 3-MMA) ============
// out[b,d,n] = (sum_m V[d,m] * P_unnorm[n,m]) * rinv[n] + x[b,d,n]
#define PV_ROWPAD 40
#define PV_MAT_HALVES (128 * PV_ROWPAD)
#define PV_STAGE_HALVES (4 * PV_MAT_HALVES)
#define PV_SMEM_BYTES (2 * PV_STAGE_HALVES * 2)

__global__ void __launch_bounds__(256, 2) pv_mma_kernel(
    const float* __restrict__ x, float* __restrict__ out)
{
    extern __shared__ __nv_bfloat16 sm[];
    const u32 sbase = smem_u32(sm);

    const int tid  = threadIdx.x;
    const int wid  = tid >> 5, lane = tid & 31;
    const int wm   = wid >> 1;
    const int wn   = wid & 1;
    const int b    = blockIdx.z;
    const int d0   = blockIdx.y * 128;
    const int n0   = blockIdx.x * 128;

    const __nv_bfloat16* vh = g_vh + ((size_t)b * CH + d0) * N_PIX;
    const __nv_bfloat16* vl = g_vl + ((size_t)b * CH + d0) * N_PIX;
    const __nv_bfloat16* ph = g_ph + ((size_t)b * N_PIX + n0) * N_PIX;
    const __nv_bfloat16* pl = g_pl + ((size_t)b * N_PIX + n0) * N_PIX;

    float acc[2][8][4];
#pragma unroll
    for (int i = 0; i < 2; i++)
#pragma unroll
        for (int j = 0; j < 8; j++)
#pragma unroll
            for (int q = 0; q < 4; q++) acc[i][j][q] = 0.f;

    const int a_row = wm * 32 + (lane & 15);
    const int a_col = (lane >> 4) << 3;
    const int b_row = wn * 64 + (lane & 7) + ((lane >> 4) & 1) * 8;
    const int b_col = ((lane >> 3) & 1) * 8;

    auto load_stage = [&](int stg, int m0) {
#pragma unroll
        for (int j = 0; j < 8; ++j) {
            int idx = tid + j * 256;
            int mat = idx >> 9;
            int within = idx & 511;
            int row = within >> 2;
            int c4 = within & 3;
            const __nv_bfloat16* src =
                (mat == 0 ? vh : mat == 1 ? vl : mat == 2 ? ph : pl)
                + (size_t)row * N_PIX + m0 + c4 * 8;
            u32 dst = sbase + (u32)(stg * PV_STAGE_HALVES + mat * PV_MAT_HALVES
                                    + row * PV_ROWPAD + c4 * 8) * 2;
            cp16(dst, src);
        }
    };

    load_stage(0, 0);
    CP_COMMIT();

    const int NSTG = N_PIX / 32;
    for (int s = 0; s < NSTG; ++s) {
        if (s + 1 < NSTG) {
            load_stage((s + 1) & 1, (s + 1) * 32);
            CP_COMMIT();
            CP_WAIT1();
        } else {
            CP_WAIT0();
        }
        __syncthreads();

        const u32 stgb = sbase + (u32)((s & 1) * PV_STAGE_HALVES) * 2;
        const u32 ah_b = stgb;
        const u32 al_b = stgb + PV_MAT_HALVES * 2;
        const u32 bh_b = stgb + 2 * PV_MAT_HALVES * 2;
        const u32 bl_b = stgb + 3 * PV_MAT_HALVES * 2;

#pragma unroll
        for (int kk = 0; kk < 32; kk += 16) {
            u32 ah[2][4], al[2][4];
#pragma unroll
            for (int mf = 0; mf < 2; mf++) {
                u32 ao = (u32)((a_row + mf * 16) * PV_ROWPAD + a_col + kk) * 2;
                ldm4(ah_b + ao, ah[mf][0], ah[mf][1], ah[mf][2], ah[mf][3]);
                ldm4(al_b + ao, al[mf][0], al[mf][1], al[mf][2], al[mf][3]);
            }
#pragma unroll
            for (int nf2 = 0; nf2 < 4; nf2++) {
                u32 bo = (u32)((b_row + nf2 * 16) * PV_ROWPAD + b_col + kk) * 2;
                u32 bh[4], bl[4];
                ldm4(bh_b + bo, bh[0], bh[1], bh[2], bh[3]);
                ldm4(bl_b + bo, bl[0], bl[1], bl[2], bl[3]);
#pragma unroll
                for (int mf = 0; mf < 2; mf++) {
                    mma16816(acc[mf][nf2 * 2],     ah[mf], bh[0], bh[1]);
                    mma16816(acc[mf][nf2 * 2],     ah[mf], bl[0], bl[1]);
                    mma16816(acc[mf][nf2 * 2],     al[mf], bh[0], bh[1]);
                    mma16816(acc[mf][nf2 * 2 + 1], ah[mf], bh[2], bh[3]);
                    mma16816(acc[mf][nf2 * 2 + 1], ah[mf], bl[2], bl[3]);
                    mma16816(acc[mf][nf2 * 2 + 1], al[mf], bh[2], bh[3]);
                }
            }
        }
        __syncthreads();
    }

    const int er = lane >> 2;
    const int ec = 2 * (lane & 3);
    const float* rb = g_rinv + (size_t)b * N_PIX;
#pragma unroll
    for (int nf = 0; nf < 8; nf++) {
        const int n = n0 + wn * 64 + nf * 8 + ec;
        float2 rv = *(const float2*)(rb + n);
#pragma unroll
        for (int mf = 0; mf < 2; mf++) {
            const int d = d0 + wm * 32 + mf * 16 + er;
            size_t o1 = ((size_t)b * CH + d) * N_PIX + n;
            size_t o2 = o1 + (size_t)8 * N_PIX;
            float2 x1 = *(const float2*)(x + o1);
            float2 x2 = *(const float2*)(x + o2);
            *(float2*)(out + o1) = make_float2(acc[mf][nf][0] * rv.x + x1.x,
                                               acc[mf][nf][1] * rv.y + x1.y);
            *(float2*)(out + o2) = make_float2(acc[mf][nf][2] * rv.x + x2.x,
                                               acc[mf][nf][3] * rv.y + x2.y);
        }
    }
}

// ================== launch =========================================================
extern "C" void kernel_launch(void* const* d_in, const int* in_sizes, int n_in,
                              void* d_out, int out_size)
{
    (void)in_sizes; (void)n_in; (void)out_size;
    const float* x  = (const float*)d_in[0];
    const float* Wq = (const float*)d_in[1];
    const float* bq = (const float*)d_in[2];
    const float* Wk = (const float*)d_in[3];
    const float* bk = (const float*)d_in[4];
    const float* Wv = (const float*)d_in[5];
    const float* bv = (const float*)d_in[6];
    float* out = (float*)d_out;

    static int smem_set = 0;
    if (!smem_set) {
        cudaFuncSetAttribute(pv_mma_kernel,
                             cudaFuncAttributeMaxDynamicSharedMemorySize, PV_SMEM_BYTES);
        smem_set = 1;
    }

    dim3 blk2(16, 16);
    proj_qk_kernel<<<dim3(16, 4), 256>>>(x, Wq, bq, Wk, bk);
    proj_v_kernel<<<dim3(64, 4, 4), blk2>>>(x, Wv, bv);
    energy_exp_kernel<<<dim3(64, 64, 4), blk2>>>();
    rsum_kernel<<<64, 256>>>();
    pv_mma_kernel<<<dim3(32, 2, 4), 256, PV_SMEM_BYTES>>>(x, out);
}

// round 7
// speedup vs baseline: 3.1366x; 1.3387x over previous
#include <cuda_runtime.h>
#include <cuda_bf16.h>
#include <cstdint>

#define N_PIX 4096
#define BATCH 4
#define CH    256
#define DQK   32

typedef unsigned long long u64;
typedef unsigned int u32;

// ---------------- scratch (device globals) ------------------------------------------
__device__ __nv_bfloat16 g_qh[(size_t)BATCH * N_PIX * DQK];  // Q hi [b][n][32]
__device__ __nv_bfloat16 g_ql[(size_t)BATCH * N_PIX * DQK];  // Q lo
__device__ __nv_bfloat16 g_kh[(size_t)BATCH * N_PIX * DQK];  // K hi [b][m][32]
__device__ __nv_bfloat16 g_kl[(size_t)BATCH * N_PIX * DQK];  // K lo
__device__ __nv_bfloat16 g_vh[(size_t)BATCH * CH * N_PIX];   // V hi [b][d][m]
__device__ __nv_bfloat16 g_vl[(size_t)BATCH * CH * N_PIX];   // V lo

// ---------------- f32x2 helpers ------------------------------------------------------
__device__ __forceinline__ u64 fma2(u64 a, u64 b, u64 c) {
    u64 d;
    asm("fma.rn.f32x2 %0, %1, %2, %3;" : "=l"(d) : "l"(a), "l"(b), "l"(c));
    return d;
}
__device__ __forceinline__ u64 pack2(float x, float y) {
    u64 r;
    asm("mov.b64 %0, {%1, %2};" : "=l"(r) : "f"(x), "f"(y));
    return r;
}
__device__ __forceinline__ float2 unpack2(u64 v) {
    float2 r;
    asm("mov.b64 {%0, %1}, %2;" : "=f"(r.x), "=f"(r.y) : "l"(v));
    return r;
}

// ---------------- split-bf16 helpers --------------------------------------------------
__device__ __forceinline__ void split2(float a, float b, u32& hi, u32& lo) {
    __nv_bfloat162 h = __floats2bfloat162_rn(a, b);     // .x = a (low), .y = b (high)
    u32 hraw = *(const u32*)&h;
    float ha = __uint_as_float(hraw << 16);
    float hb = __uint_as_float(hraw & 0xFFFF0000u);
    __nv_bfloat162 l = __floats2bfloat162_rn(a - ha, b - hb);
    hi = hraw;
    lo = *(const u32*)&l;
}
__device__ __forceinline__ void split_store4(__nv_bfloat16* hp, __nv_bfloat16* lp,
                                             float f0, float f1, float f2, float f3)
{
    u32 h0, l0, h1, l1;
    split2(f0, f1, h0, l0);
    split2(f2, f3, h1, l1);
    *(uint2*)hp = make_uint2(h0, h1);
    *(uint2*)lp = make_uint2(l0, l1);
}

// ---------------- smem / cp.async / mma helpers -------------------------------------
__device__ __forceinline__ u32 smem_u32(const void* p) {
    u32 a;
    asm("{ .reg .u64 t; cvta.to.shared.u64 t, %1; cvt.u32.u64 %0, t; }" : "=r"(a) : "l"(p));
    return a;
}
__device__ __forceinline__ void cp16(u32 d, const void* s) {
    asm volatile("cp.async.cg.shared.global [%0], [%1], 16;" :: "r"(d), "l"(s));
}
#define CP_COMMIT() asm volatile("cp.async.commit_group;" ::: "memory")
#define CP_WAIT2()  asm volatile("cp.async.wait_group 2;" ::: "memory")
#define CP_WAIT1()  asm volatile("cp.async.wait_group 1;" ::: "memory")
#define CP_WAIT0()  asm volatile("cp.async.wait_group 0;" ::: "memory")

__device__ __forceinline__ void ldm4(u32 addr, u32& r0, u32& r1, u32& r2, u32& r3) {
    asm volatile("ldmatrix.sync.aligned.m8n8.x4.shared.b16 {%0,%1,%2,%3}, [%4];"
                 : "=r"(r0), "=r"(r1), "=r"(r2), "=r"(r3) : "r"(addr));
}
__device__ __forceinline__ void mma16816(float* c, const u32* a, u32 b0, u32 b1) {
    asm volatile(
        "mma.sync.aligned.m16n8k16.row.col.f32.bf16.bf16.f32 "
        "{%0,%1,%2,%3}, {%4,%5,%6,%7}, {%8,%9}, {%0,%1,%2,%3};"
        : "+f"(c[0]), "+f"(c[1]), "+f"(c[2]), "+f"(c[3])
        : "r"(a[0]), "r"(a[1]), "r"(a[2]), "r"(a[3]), "r"(b0), "r"(b1));
}

// ================== kernel 1: q/k projection (writes split-bf16) ===================
__global__ void __launch_bounds__(256) proj_qk_kernel(
    const float* __restrict__ x,
    const float* __restrict__ Wq, const float* __restrict__ bq,
    const float* __restrict__ Wk, const float* __restrict__ bk)
{
    __shared__ float sX[32 * 260];
    __shared__ float sW[32 * 68];

    const int tid = threadIdx.x;
    const int g = tid & 31;
    const int h = tid >> 5;
    const int b = blockIdx.y;
    const int n0 = blockIdx.x * 256;
    const bool isq = (h < 4);
    const int dbase = (h & 3) * 8;
    const int woff = (isq ? 0 : 32) + dbase;

    u64 acc[8][4];
#pragma unroll
    for (int i = 0; i < 8; i++)
#pragma unroll
        for (int p = 0; p < 4; p++) acc[i][p] = 0;

    for (int c0 = 0; c0 < CH; c0 += 32) {
        __syncthreads();
#pragma unroll
        for (int pass = 0; pass < 4; ++pass) {
            int cc = h + pass * 8;
            const float* src = x + ((size_t)b * CH + c0 + cc) * N_PIX + n0 + g * 8;
            float4 v0 = *(const float4*)src;
            float4 v1 = *(const float4*)(src + 4);
            float* dst = sX + g * 260 + cc * 8;
            *(float4*)dst = v0;
            *(float4*)(dst + 4) = v1;
        }
        {
            int d = tid & 31;
            int c4 = (tid >> 5) * 4;
            float4 wq4 = *(const float4*)(Wq + d * CH + c0 + c4);
            float4 wk4 = *(const float4*)(Wk + d * CH + c0 + c4);
            sW[(c4 + 0) * 68 + d] = wq4.x; sW[(c4 + 1) * 68 + d] = wq4.y;
            sW[(c4 + 2) * 68 + d] = wq4.z; sW[(c4 + 3) * 68 + d] = wq4.w;
            sW[(c4 + 0) * 68 + 32 + d] = wk4.x; sW[(c4 + 1) * 68 + 32 + d] = wk4.y;
            sW[(c4 + 2) * 68 + 32 + d] = wk4.z; sW[(c4 + 3) * 68 + 32 + d] = wk4.w;
        }
        __syncthreads();

#pragma unroll 8
        for (int cc = 0; cc < 32; ++cc) {
            const float* xp = sX + g * 260 + cc * 8;
            float4 xa = *(const float4*)xp;
            float4 xb = *(const float4*)(xp + 4);
            u64 xpair[4] = {pack2(xa.x, xa.y), pack2(xa.z, xa.w),
                            pack2(xb.x, xb.y), pack2(xb.z, xb.w)};
            const float* wp = sW + cc * 68 + woff;
            float4 w0 = *(const float4*)wp;
            float4 w1 = *(const float4*)(wp + 4);
            float wv[8] = {w0.x, w0.y, w0.z, w0.w, w1.x, w1.y, w1.z, w1.w};
#pragma unroll
            for (int i = 0; i < 8; i++) {
                u64 wd = pack2(wv[i], wv[i]);
#pragma unroll
                for (int p = 0; p < 4; p++)
                    acc[i][p] = fma2(wd, xpair[p], acc[i][p]);
            }
        }
    }

    const float* bias = isq ? bq : bk;
    float bb[8];
#pragma unroll
    for (int i = 0; i < 8; i++) bb[i] = bias[dbase + i];
    __nv_bfloat16* oh = (isq ? g_qh : g_kh) + ((size_t)b * N_PIX + n0 + g * 8) * DQK + dbase;
    __nv_bfloat16* ol = (isq ? g_ql : g_kl) + ((size_t)b * N_PIX + n0 + g * 8) * DQK + dbase;
#pragma unroll
    for (int j = 0; j < 8; j++) {
        float v[8];
#pragma unroll
        for (int i = 0; i < 8; i++) {
            float2 t = unpack2(acc[i][j >> 1]);
            v[i] = ((j & 1) ? t.y : t.x) + bb[i];
        }
        u32 hh[4], ll[4];
        split2(v[0], v[1], hh[0], ll[0]);
        split2(v[2], v[3], hh[1], ll[1]);
        split2(v[4], v[5], hh[2], ll[2]);
        split2(v[6], v[7], hh[3], ll[3]);
        *(uint4*)(oh + (size_t)j * DQK) = make_uint4(hh[0], hh[1], hh[2], hh[3]);
        *(uint4*)(ol + (size_t)j * DQK) = make_uint4(ll[0], ll[1], ll[2], ll[3]);
    }
}

// ================== kernel 2: v projection (writes split-bf16 V) ===================
__global__ void __launch_bounds__(256) proj_v_kernel(
    const float* __restrict__ x, const float* __restrict__ Wv, const float* __restrict__ bv)
{
    __shared__ float sA[32][68];
    __shared__ float sB[32][68];

    int b  = blockIdx.z;
    int n0 = blockIdx.x * 64;
    int d0 = blockIdx.y * 64;
    int tx = threadIdx.x, ty = threadIdx.y, tid = ty * 16 + tx;

    float acc[4][4] = {};

    for (int c0 = 0; c0 < CH; c0 += 32) {
        for (int idx = tid; idx < 512; idx += 256) {
            int r = idx >> 3, q = idx & 7;
            float4 w = *(const float4*)(Wv + (size_t)(d0 + r) * CH + c0 + q * 4);
            sA[q * 4 + 0][r] = w.x; sA[q * 4 + 1][r] = w.y;
            sA[q * 4 + 2][r] = w.z; sA[q * 4 + 3][r] = w.w;

            int r2 = idx >> 4, q2 = idx & 15;
            float4 xv = *(const float4*)(x + ((size_t)b * CH + c0 + r2) * N_PIX + n0 + q2 * 4);
            *(float4*)&sB[r2][q2 * 4] = xv;
        }
        __syncthreads();

#pragma unroll
        for (int k = 0; k < 32; k++) {
            float4 a4 = *(const float4*)&sA[k][ty * 4];
            float4 b4 = *(const float4*)&sB[k][tx * 4];
            float av[4] = {a4.x, a4.y, a4.z, a4.w};
            float bw[4] = {b4.x, b4.y, b4.z, b4.w};
#pragma unroll
            for (int i = 0; i < 4; i++)
#pragma unroll
                for (int j = 0; j < 4; j++)
                    acc[i][j] += av[i] * bw[j];
        }
        __syncthreads();
    }

#pragma unroll
    for (int i = 0; i < 4; i++) {
        int d = d0 + ty * 4 + i;
        float bias = bv[d];
        size_t base = ((size_t)b * CH + d) * N_PIX + n0 + tx * 4;
        split_store4(g_vh + base, g_vl + base,
                     acc[i][0] + bias, acc[i][1] + bias,
                     acc[i][2] + bias, acc[i][3] + bias);
    }
}

// ================== kernel 3: fused attention (E->exp->PV, all in one) =============
// CTA: 128 queries (n0) x 128 channels (d0); loops m over N_PIX in 128-tiles.
#define FA_QH   0u           // 128 x 40 halves
#define FA_QL   10240u
#define FA_K    20480u       // 2 bufs x (hi 10240 + lo 10240)
#define FA_KBUF 20480u
#define FA_KLO  10240u
#define FA_VH   61440u       // 128 x 136 halves
#define FA_VL   96256u
#define FA_PH   131072u
#define FA_PL   165888u
#define FA_SROW 200704u      // 128 floats
#define FA_SINV 201216u      // 128 floats
#define FA_SMEM 201728u

__global__ void __launch_bounds__(256, 1) fused_attn_kernel(
    const float* __restrict__ x, float* __restrict__ out)
{
    extern __shared__ char sm[];
    const u32 S = smem_u32(sm);

    const int tid = threadIdx.x;
    const int w = tid >> 5, lane = tid & 31;
    const int b  = blockIdx.z;
    const int n0 = blockIdx.x * 128;
    const int d0 = blockIdx.y * 128;

    const __nv_bfloat16* qh = g_qh + ((size_t)b * N_PIX + n0) * DQK;
    const __nv_bfloat16* ql = g_ql + ((size_t)b * N_PIX + n0) * DQK;
    const __nv_bfloat16* kh = g_kh + (size_t)b * N_PIX * DQK;
    const __nv_bfloat16* kl = g_kl + (size_t)b * N_PIX * DQK;
    const __nv_bfloat16* vh = g_vh + ((size_t)b * CH + d0) * N_PIX;
    const __nv_bfloat16* vl = g_vl + ((size_t)b * CH + d0) * N_PIX;

    auto load_qk32 = [&](u32 sbase, const __nv_bfloat16* hsrc, const __nv_bfloat16* lsrc) {
#pragma unroll
        for (int j = 0; j < 4; ++j) {
            int idx = tid + j * 256;
            int mat = idx >> 9;
            int within = idx & 511;
            int row = within >> 2, c = within & 3;
            const __nv_bfloat16* src = (mat ? lsrc : hsrc) + (size_t)row * DQK + c * 8;
            cp16(sbase + (u32)mat * 10240u + (u32)(row * 40 + c * 8) * 2, src);
        }
    };
    auto load_v = [&](int m0) {
#pragma unroll
        for (int j = 0; j < 16; ++j) {
            int idx = tid + j * 256;
            int mat = idx >> 11;
            int within = idx & 2047;
            int row = within >> 4, c = within & 15;
            const __nv_bfloat16* src = (mat ? vl : vh) + (size_t)row * N_PIX + m0 + c * 8;
            cp16(S + (mat ? FA_VL : FA_VH) + (u32)(row * 136 + c * 8) * 2, src);
        }
    };

    // ---- prologue ----
    load_qk32(S + FA_QH, qh, ql);
    load_qk32(S + FA_K, kh, kl);
    load_v(0);
    CP_COMMIT();
    load_qk32(S + FA_K + FA_KBUF, kh + 128 * DQK, kl + 128 * DQK);
    CP_COMMIT();
    CP_WAIT1();
    __syncthreads();

    float accO[16][4];
#pragma unroll
    for (int i = 0; i < 16; i++)
#pragma unroll
        for (int q = 0; q < 4; q++) accO[i][q] = 0.f;
    float rs0 = 0.f, rs1 = 0.f;

    const int arow = w * 16 + (lane & 15);
    const int acol = (lane >> 4) << 3;
    const int brow = (lane & 7) + ((lane >> 4) & 1) * 8;
    const int bcol = ((lane >> 3) & 1) * 8;

    const int NT = N_PIX / 128;  // 32 m-tiles
    for (int t = 0; t < NT; ++t) {
        CP_WAIT2();
        __syncthreads();

        // ---- E phase ----
        const u32 kb = S + FA_K + (u32)(t & 1) * FA_KBUF;
        float accE[16][4];
#pragma unroll
        for (int i = 0; i < 16; i++)
#pragma unroll
            for (int q = 0; q < 4; q++) accE[i][q] = 0.f;

#pragma unroll
        for (int kk = 0; kk < 32; kk += 16) {
            u32 ah[4], al[4];
            u32 ao = (u32)(arow * 40 + acol + kk) * 2;
            ldm4(S + FA_QH + ao, ah[0], ah[1], ah[2], ah[3]);
            ldm4(S + FA_QL + ao, al[0], al[1], al[2], al[3]);
#pragma unroll
            for (int nf = 0; nf < 8; nf++) {
                u32 bo = (u32)((nf * 16 + brow) * 40 + bcol + kk) * 2;
                u32 bh[4], bl[4];
                ldm4(kb + bo, bh[0], bh[1], bh[2], bh[3]);
                ldm4(kb + FA_KLO + bo, bl[0], bl[1], bl[2], bl[3]);
                mma16816(accE[nf * 2],     ah, bh[0], bh[1]);
                mma16816(accE[nf * 2],     ah, bl[0], bl[1]);
                mma16816(accE[nf * 2],     al, bh[0], bh[1]);
                mma16816(accE[nf * 2 + 1], ah, bh[2], bh[3]);
                mma16816(accE[nf * 2 + 1], ah, bl[2], bl[3]);
                mma16816(accE[nf * 2 + 1], al, bh[2], bh[3]);
            }
        }

        // ---- exp + rowsum + split-bf16 store to P smem ----
        {
            const int prow = w * 16 + (lane >> 2);
            const int pcol = 2 * (lane & 3);
#pragma unroll
            for (int nf = 0; nf < 16; nf++) {
                float e0 = __expf(accE[nf][0]);
                float e1 = __expf(accE[nf][1]);
                float e2 = __expf(accE[nf][2]);
                float e3 = __expf(accE[nf][3]);
                rs0 += e0 + e1;
                rs1 += e2 + e3;
                u32 hi0, lo0, hi1, lo1;
                split2(e0, e1, hi0, lo0);
                split2(e2, e3, hi1, lo1);
                u32 off0 = (u32)(prow * 136 + nf * 8 + pcol) * 2;
                u32 off1 = off0 + 8u * 136u * 2u;
                *(u32*)(sm + FA_PH + off0) = hi0;
                *(u32*)(sm + FA_PL + off0) = lo0;
                *(u32*)(sm + FA_PH + off1) = hi1;
                *(u32*)(sm + FA_PL + off1) = lo1;
            }
        }
        __syncthreads();

        CP_WAIT1();

        // ---- PV phase ----
#pragma unroll
        for (int ks = 0; ks < 8; ks++) {
            u32 ah[4], al[4];
            u32 ao = (u32)(arow * 136 + acol + ks * 16) * 2;
            ldm4(S + FA_VH + ao, ah[0], ah[1], ah[2], ah[3]);
            ldm4(S + FA_VL + ao, al[0], al[1], al[2], al[3]);
#pragma unroll
            for (int nf = 0; nf < 8; nf++) {
                u32 bo = (u32)((nf * 16 + brow) * 136 + bcol + ks * 16) * 2;
                u32 bh[4], bl[4];
                ldm4(S + FA_PH + bo, bh[0], bh[1], bh[2], bh[3]);
                ldm4(S + FA_PL + bo, bl[0], bl[1], bl[2], bl[3]);
                mma16816(accO[nf * 2],     ah, bh[0], bh[1]);
                mma16816(accO[nf * 2],     ah, bl[0], bl[1]);
                mma16816(accO[nf * 2],     al, bh[0], bh[1]);
                mma16816(accO[nf * 2 + 1], ah, bh[2], bh[3]);
                mma16816(accO[nf * 2 + 1], ah, bl[2], bl[3]);
                mma16816(accO[nf * 2 + 1], al, bh[2], bh[3]);
            }
        }
        __syncthreads();

        // ---- issue next loads ----
        {
            int tv = t + 1 < NT ? t + 1 : NT - 1;
            int tk = t + 2 < NT ? t + 2 : NT - 1;
            load_v(tv * 128);
            CP_COMMIT();
            load_qk32(S + FA_K + (u32)(t & 1) * FA_KBUF,
                      kh + (size_t)tk * 128 * DQK, kl + (size_t)tk * 128 * DQK);
            CP_COMMIT();
        }
    }

    // ---- row sums: reduce across the quad (lanes sharing a row), then -> 1/sum ----
    rs0 += __shfl_xor_sync(0xffffffffu, rs0, 1);
    rs0 += __shfl_xor_sync(0xffffffffu, rs0, 2);
    rs1 += __shfl_xor_sync(0xffffffffu, rs1, 1);
    rs1 += __shfl_xor_sync(0xffffffffu, rs1, 2);
    if ((lane & 3) == 0) {
        ((float*)(sm + FA_SROW))[w * 16 + (lane >> 2)] = rs0;
        ((float*)(sm + FA_SROW))[w * 16 + (lane >> 2) + 8] = rs1;
    }
    __syncthreads();
    if (tid < 128)
        ((float*)(sm + FA_SINV))[tid] = 1.0f / ((float*)(sm + FA_SROW))[tid];
    __syncthreads();

    // ---- epilogue: out = accO * rinv[n] + x ----
    const float* sinv = (const float*)(sm + FA_SINV);
    const int er = lane >> 2;
    const int ec = 2 * (lane & 3);
#pragma unroll
    for (int nf = 0; nf < 16; nf++) {
        const int n = nf * 8 + ec;
        float2 rv = *(const float2*)(sinv + n);
        const int d = d0 + w * 16 + er;
        size_t o1 = ((size_t)b * CH + d) * N_PIX + n0 + n;
        size_t o2 = o1 + (size_t)8 * N_PIX;
        float2 x1 = *(const float2*)(x + o1);
        float2 x2 = *(const float2*)(x + o2);
        *(float2*)(out + o1) = make_float2(accO[nf][0] * rv.x + x1.x,
                                           accO[nf][1] * rv.y + x1.y);
        *(float2*)(out + o2) = make_float2(accO[nf][2] * rv.x + x2.x,
                                           accO[nf][3] * rv.y + x2.y);
    }
}

// ================== launch =========================================================
extern "C" void kernel_launch(void* const* d_in, const int* in_sizes, int n_in,
                              void* d_out, int out_size)
{
    (void)in_sizes; (void)n_in; (void)out_size;
    const float* x  = (const float*)d_in[0];
    const float* Wq = (const float*)d_in[1];
    const float* bq = (const float*)d_in[2];
    const float* Wk = (const float*)d_in[3];
    const float* bk = (const float*)d_in[4];
    const float* Wv = (const float*)d_in[5];
    const float* bv = (const float*)d_in[6];
    float* out = (float*)d_out;

    static int smem_set = 0;
    if (!smem_set) {
        cudaFuncSetAttribute(fused_attn_kernel,
                             cudaFuncAttributeMaxDynamicSharedMemorySize, FA_SMEM);
        smem_set = 1;
    }

    dim3 blk2(16, 16);
    proj_qk_kernel<<<dim3(16, 4), 256>>>(x, Wq, bq, Wk, bk);
    proj_v_kernel<<<dim3(64, 4, 4), blk2>>>(x, Wv, bv);
    fused_attn_kernel<<<dim3(32, 2, 4), 256, FA_SMEM>>>(x, out);
}